// round 17
// baseline (speedup 1.0000x reference)
#include <cuda_runtime.h>
#include <cuda_fp16.h>
#include <math.h>

#define NN 50000
#define NP 50048
#define EE 400000
#define RR 4
#define MM (RR*NN)
#define SCAN_BLOCKS ((MM + 4095) / 4096)   // 49

#define FMA2(acc, w, a) asm("fma.rn.f32x2 %0, %1, %2, %0;" : "+l"(acc) : "l"(w), "l"(a))
#define PACK2(dst, lo, hi) asm("mov.b64 %0, {%1, %2};" : "=l"(dst) : "f"(lo), "f"(hi))
#define UNPACK2(lo, hi, src) asm("mov.b64 {%0, %1}, %2;" : "=f"(lo), "=f"(hi) : "l"(src))
#define CP_ASYNC16(saddr, gptr) \
    asm volatile("cp.async.cg.shared.global [%0], [%1], 16;" :: "r"(saddr), "l"(gptr))
#define CP_COMMIT() asm volatile("cp.async.commit_group;")
#define CP_WAIT0() asm volatile("cp.async.wait_group 0;" ::: "memory")

__device__ __forceinline__ unsigned smem_u32(const void* p) {
    return (unsigned)__cvta_generic_to_shared(p);
}

// ---------------- device scratch ----------------
__device__ __align__(16) float g_h2[NP * 64];
__device__ __align__(16) __half2 g_Hr[(size_t)RR * NP * 64];
__device__ __align__(16) float g_es[RR * NP * 2];
__device__ __align__(16) float g_ed[RR * NP * 2];
__device__ __align__(16) __half g_Fh[(size_t)NN * 512];
__device__ int g_deg[MM];           // zero at entry: zero-init first call, re-zeroed by k_scan
__device__ int g_indptr[MM + 1];
__device__ int g_cursor[MM];
__device__ int g_nbr[2 * EE + 8];   // +8 pad: prefetch may read past the end (discarded)
__device__ volatile int g_flag[64]; // lookback flags: aggregate | 0x40000000; reset by k_hist

// ---------------- CSR build ----------------
__global__ void k_hist(const int* __restrict__ ei, const float* __restrict__ ew) {
    if (blockIdx.x == 0 && threadIdx.x < 64) g_flag[threadIdx.x] = 0;  // reset scan flags
    int e = blockIdx.x * 256 + threadIdx.x;
    if (e >= EE) return;
    int s = ei[e];
    int d = ei[EE + e];
    float w = ew[e];
    if (w > 0.f) {
        atomicAdd(&g_deg[0 * NN + d], 1);
        atomicAdd(&g_deg[1 * NN + s], 1);
    } else if (w < 0.f) {
        atomicAdd(&g_deg[2 * NN + d], 1);
        atomicAdd(&g_deg[3 * NN + s], 1);
    }
}

// single-pass scan with decoupled lookback: indptr + cursor + deg reset in one kernel.
// 49 blocks co-resident on 148 SMs -> no deadlock. (Validated correct in round 10.)
__global__ void k_scan() {
    __shared__ int sd[512];
    int t = threadIdx.x;
    int b = blockIdx.x;
    int base = b * 4096 + t * 8;
    int v[8];
    int s = 0;
#pragma unroll
    for (int i = 0; i < 8; i++) {
        int idx = base + i;
        int x = (idx < MM) ? g_deg[idx] : 0;
        v[i] = s;
        s += x;
    }
    sd[t] = s;
    __syncthreads();
    int tot = s;
    for (int off = 1; off < 512; off <<= 1) {
        int y = (t >= off) ? sd[t - off] : 0;
        __syncthreads();
        sd[t] += y;
        __syncthreads();
    }
    int excl = sd[t] - tot;
    int blktot = sd[511];
    if (t == 0) g_flag[b] = blktot | 0x40000000;   // publish aggregate

    int pre = 0;
    if (t < b) {                                   // one thread per predecessor
        int f;
        do { f = g_flag[t]; } while (f == 0);
        pre = f & 0x3FFFFFFF;
    }
    __syncthreads();
    sd[t] = pre;
    __syncthreads();
    if (t < 256) sd[t] += sd[t + 256];
    __syncthreads();
    if (t < 128) sd[t] += sd[t + 128];
    __syncthreads();
    if (t < 64) sd[t] += sd[t + 64];
    __syncthreads();
    if (t < 32) {
        int x = sd[t] + sd[t + 32];
#pragma unroll
        for (int o = 16; o; o >>= 1) x += __shfl_down_sync(0xffffffffu, x, o);
        if (t == 0) sd[0] = x;
    }
    __syncthreads();
    int offset = sd[0];

    int start = offset + excl;
#pragma unroll
    for (int i = 0; i < 8; i++) {
        int idx = base + i;
        if (idx < MM) {
            int w = start + v[i];
            g_indptr[idx] = w;
            g_cursor[idx] = w;
            g_deg[idx] = 0;          // restore invariant for next call
        }
    }
    if (b == SCAN_BLOCKS - 1 && t == 511) g_indptr[MM] = offset + blktot;
}

__global__ void k_scatter(const int* __restrict__ ei, const float* __restrict__ ew) {
    int e = blockIdx.x * 256 + threadIdx.x;
    if (e >= EE) return;
    int s = ei[e];
    int d = ei[EE + e];
    float w = ew[e];
    if (w > 0.f) {
        int p0 = atomicAdd(&g_cursor[0 * NN + d], 1); g_nbr[p0] = s;
        int p1 = atomicAdd(&g_cursor[1 * NN + s], 1); g_nbr[p1] = d;
    } else if (w < 0.f) {
        int p2 = atomicAdd(&g_cursor[2 * NN + d], 1); g_nbr[p2] = s;
        int p3 = atomicAdd(&g_cursor[3 * NN + s], 1); g_nbr[p3] = d;
    }
}

// ---------------- per-relation feature GEMM + fused attention logits ----------------
__global__ __launch_bounds__(128) void k_feat(const float* __restrict__ xin,
                                              const float* __restrict__ W,
                                              const float* __restrict__ asrc,
                                              const float* __restrict__ adst,
                                              int l, int useX) {
    __shared__ __align__(16) float Ws[64 * 128];
    __shared__ __align__(16) float hsT[64 * 68];

    const float* hin = useX ? xin : g_h2;
    const int t = threadIdx.x;
    const int r = blockIdx.y;
    const int jc = t & 31;
    const int half = t >> 5;
    const float* Wp = W + (size_t)(l * RR + r) * 64 * 128;

    unsigned s_Ws = smem_u32(Ws);
#pragma unroll
    for (int i = 0; i < 16; i++) {
        int c4 = t + i * 128;
        CP_ASYNC16(s_Ws + c4 * 16, Wp + c4 * 4);
    }
    CP_COMMIT();

    int n0 = blockIdx.x * 64;
    for (int q = t; q < 64 * 64; q += 128) {
        int nn = q >> 6, k = q & 63;
        int n = n0 + nn;
        hsT[k * 68 + nn] = (n < NN) ? hin[(size_t)n * 64 + k] : 0.f;
    }
    CP_WAIT0();
    __syncthreads();

    unsigned long long acc[4][8];
#pragma unroll
    for (int c = 0; c < 4; c++)
#pragma unroll
        for (int p = 0; p < 8; p++) acc[c][p] = 0ull;

#pragma unroll 2
    for (int k = 0; k < 64; k++) {
        float w0 = Ws[k * 128 + jc];
        float w1 = Ws[k * 128 + jc + 32];
        float w2 = Ws[k * 128 + jc + 64];
        float w3 = Ws[k * 128 + jc + 96];
        unsigned long long wp0, wp1, wp2, wp3;
        PACK2(wp0, w0, w0); PACK2(wp1, w1, w1);
        PACK2(wp2, w2, w2); PACK2(wp3, w3, w3);
        const ulonglong2* hp = (const ulonglong2*)&hsT[k * 68 + half * 16];
#pragma unroll
        for (int q = 0; q < 4; q++) {
            ulonglong2 a = hp[q];
            FMA2(acc[0][2 * q], wp0, a.x); FMA2(acc[0][2 * q + 1], wp0, a.y);
            FMA2(acc[1][2 * q], wp1, a.x); FMA2(acc[1][2 * q + 1], wp1, a.y);
            FMA2(acc[2][2 * q], wp2, a.x); FMA2(acc[2][2 * q + 1], wp2, a.y);
            FMA2(acc[3][2 * q], wp3, a.x); FMA2(acc[3][2 * q + 1], wp3, a.y);
        }
    }

    // H store (fp16)
    __half2* Hrow = g_Hr + (size_t)r * NP * 64;
    int nb = n0 + half * 16;
#pragma unroll
    for (int p = 0; p < 8; p++) {
        float l0, h0, l1, h1, l2, h2, l3, h3;
        UNPACK2(l0, h0, acc[0][p]);
        UNPACK2(l1, h1, acc[1][p]);
        UNPACK2(l2, h2, acc[2][p]);
        UNPACK2(l3, h3, acc[3][p]);
        Hrow[(size_t)(nb + 2 * p) * 64 + jc]          = __floats2half2_rn(l0, l1);
        Hrow[(size_t)(nb + 2 * p + 1) * 64 + jc]      = __floats2half2_rn(h0, h1);
        Hrow[(size_t)(nb + 2 * p) * 64 + 32 + jc]     = __floats2half2_rn(l2, l3);
        Hrow[(size_t)(nb + 2 * p + 1) * 64 + 32 + jc] = __floats2half2_rn(h2, h3);
    }

    // fused logits: value v = p*4 + hd*2 + sd, lane v keeps the reduced pair.
    const float* ap = asrc + (size_t)(l * RR + r) * 128;
    const float* dp = adst + (size_t)(l * RR + r) * 128;
    unsigned long long as0, as1, as2, as3, ad0, ad1, ad2, ad3, ONE2;
    {
        float a_, b_;
        a_ = ap[jc];      PACK2(as0, a_, a_);
        a_ = ap[jc + 32]; PACK2(as1, a_, a_);
        a_ = ap[jc + 64]; PACK2(as2, a_, a_);
        a_ = ap[jc + 96]; PACK2(as3, a_, a_);
        a_ = dp[jc];      PACK2(ad0, a_, a_);
        a_ = dp[jc + 32]; PACK2(ad1, a_, a_);
        a_ = dp[jc + 64]; PACK2(ad2, a_, a_);
        a_ = dp[jc + 96]; PACK2(ad3, a_, a_);
        a_ = 1.0f; b_ = 1.0f; PACK2(ONE2, a_, b_);
    }
    unsigned long long keep = 0ull;
#pragma unroll
    for (int p = 0; p < 8; p++) {
#pragma unroll
        for (int combo = 0; combo < 4; combo++) {
            int hd = combo >> 1, sd = combo & 1;
            unsigned long long tsum = 0ull;
            unsigned long long m0 = sd ? (hd ? ad2 : ad0) : (hd ? as2 : as0);
            unsigned long long m1 = sd ? (hd ? ad3 : ad1) : (hd ? as3 : as1);
            FMA2(tsum, m0, acc[hd * 2 + 0][p]);
            FMA2(tsum, m1, acc[hd * 2 + 1][p]);
#pragma unroll
            for (int off = 16; off; off >>= 1) {
                unsigned long long o = __shfl_xor_sync(0xffffffffu, tsum, off);
                FMA2(tsum, ONE2, o);
            }
            if (jc == p * 4 + combo) keep = tsum;
        }
    }
    {
        int p = jc >> 2, hd = (jc >> 1) & 1, sd = jc & 1;
        float vlo, vhi;
        UNPACK2(vlo, vhi, keep);
        float* dst = (sd ? g_ed : g_es) + ((size_t)r * NP + nb + 2 * p) * 2 + hd;
        dst[0] = vlo;
        dst[2] = vhi;
    }
}

// ---------------- CSR gather: 2 rows/warp, software-pipelined index prefetch ----------------
__global__ void k_gather(const float* __restrict__ gbias, int l) {
    int warp = (blockIdx.x * 256 + threadIdx.x) >> 5;
    int lane = threadIdx.x & 31;
    int hw = lane >> 4;
    int q = lane & 15;
    int gw = warp * 2 + hw;
    if (gw >= MM) return;
    int r = gw / NN;
    int d = gw - r * NN;
    int hd = q >> 3;
    int cbase = hd * 64 + 4 * (q & 7);

    const float* esr = g_es + (size_t)r * NP * 2;
    float edv = g_ed[((size_t)r * NP + d) * 2 + hd];
    const uint4* Hp = (const uint4*)(g_Hr + (size_t)r * NP * 64);

    float e0 = esr[d * 2 + hd] + edv;
    e0 = fmaxf(e0, 0.2f * e0);
    float p = __expf(e0);
    uint4 sv = Hp[(size_t)d * 16 + q];
    float2 f0 = __half22float2(*(__half2*)&sv.x);
    float2 f1 = __half22float2(*(__half2*)&sv.y);
    float2 f2 = __half22float2(*(__half2*)&sv.z);
    float2 f3 = __half22float2(*(__half2*)&sv.w);
    float a0 = p * f0.x, a4 = p * f0.y;
    float a1 = p * f1.x, a5 = p * f1.y;
    float a2 = p * f2.x, a6 = p * f2.y;
    float a3 = p * f3.x, a7 = p * f3.y;
    float den = p;
    float b0 = 0.f, b1 = 0.f, b2 = 0.f, b3 = 0.f;
    float b4 = 0.f, b5 = 0.f, b6 = 0.f, b7 = 0.f, denB = 0.f;

    int i = g_indptr[gw];
    int cnt = g_indptr[gw + 1] - i;
    // prefetch first pair (reads past row end land in next row / zero pad: valid ids)
    int j0 = g_nbr[i];
    int j1 = g_nbr[i + 1];
    while (cnt > 0) {
        int k0 = j0, k1 = j1;
        j0 = g_nbr[i + 2];            // prefetch next pair during this iteration
        j1 = g_nbr[i + 3];
        float ea = esr[k0 * 2 + hd] + edv;
        float eb = esr[k1 * 2 + hd] + edv;
        uint4 u0 = Hp[(size_t)k0 * 16 + q];
        uint4 u1 = Hp[(size_t)k1 * 16 + q];
        ea = fmaxf(ea, 0.2f * ea);
        eb = fmaxf(eb, 0.2f * eb);
        float pa = __expf(ea);
        float pb = (cnt > 1) ? __expf(eb) : 0.f;   // mask odd tail
        den += pa; denB += pb;
        float2 g0 = __half22float2(*(__half2*)&u0.x);
        float2 g1 = __half22float2(*(__half2*)&u0.y);
        float2 g2 = __half22float2(*(__half2*)&u0.z);
        float2 g3 = __half22float2(*(__half2*)&u0.w);
        a0 += pa * g0.x; a4 += pa * g0.y;
        a1 += pa * g1.x; a5 += pa * g1.y;
        a2 += pa * g2.x; a6 += pa * g2.y;
        a3 += pa * g3.x; a7 += pa * g3.y;
        float2 h0 = __half22float2(*(__half2*)&u1.x);
        float2 h1 = __half22float2(*(__half2*)&u1.y);
        float2 h2 = __half22float2(*(__half2*)&u1.z);
        float2 h3 = __half22float2(*(__half2*)&u1.w);
        b0 += pb * h0.x; b4 += pb * h0.y;
        b1 += pb * h1.x; b5 += pb * h1.y;
        b2 += pb * h2.x; b6 += pb * h2.y;
        b3 += pb * h3.x; b7 += pb * h3.y;
        i += 2;
        cnt -= 2;
    }
    den += denB;
    a0 += b0; a1 += b1; a2 += b2; a3 += b3;
    a4 += b4; a5 += b5; a6 += b6; a7 += b7;

    float inv = 1.f / den;
    const float* bp = gbias + (size_t)(l * RR + r) * 128 + cbase;
    __half2 o0 = __floats2half2_rn(a0 * inv + bp[0], a1 * inv + bp[1]);
    __half2 o1 = __floats2half2_rn(a2 * inv + bp[2], a3 * inv + bp[3]);
    __half2 o2 = __floats2half2_rn(a4 * inv + bp[32], a5 * inv + bp[33]);
    __half2 o3 = __floats2half2_rn(a6 * inv + bp[34], a7 * inv + bp[35]);
    __half* Fd = g_Fh + (size_t)d * 512 + r * 128 + cbase;
    *(uint2*)Fd = make_uint2(*(unsigned*)&o0, *(unsigned*)&o1);
    *(uint2*)(Fd + 32) = make_uint2(*(unsigned*)&o2, *(unsigned*)&o3);
}

// ---------------- MLP + residual + LayerNorm: cp.async double-buffered, fp16 F in ----------------
__global__ __launch_bounds__(128) void k_mlp(const float* __restrict__ xin,
                      const float* __restrict__ W1,
                      const float* __restrict__ b1,
                      const float* __restrict__ W2,
                      const float* __restrict__ b2,
                      const float* __restrict__ lng,
                      const float* __restrict__ lnb,
                      int l, float* __restrict__ outbuf, int isLast, int useX) {
    extern __shared__ __align__(16) float sm[];
    float* scomb = sm;                        // 16*576
    float* wbuf0 = scomb + 16 * 576;          // 4096
    float* wbuf1 = wbuf0 + 4096;              // 4096
    float* sRed = wbuf1 + 4096;               // 64

    const float* hin = useX ? xin : g_h2;
    float* hout = isLast ? outbuf : g_h2;

    int tid = threadIdx.x;
    int j = tid & 63;
    int g = tid >> 6;
    int lane = tid & 31;
    int w2 = (tid >> 5) & 1;
    int n0 = blockIdx.x * 16;

    const float* W1p = W1 + (size_t)l * 576 * 64;
    const float* W2p = W2 + (size_t)l * 4096;

    unsigned s_scomb = smem_u32(scomb);
    unsigned s_w0 = smem_u32(wbuf0);

#pragma unroll
    for (int i = 0; i < 2; i++) {
        int c4 = tid + i * 128;
        int nn = c4 >> 4, k4 = c4 & 15;
        CP_ASYNC16(s_scomb + (nn * 576 + k4 * 4) * 4,
                   hin + (size_t)(n0 + nn) * 64 + k4 * 4);
    }
#pragma unroll
    for (int i = 0; i < 8; i++) {
        int c4 = tid + i * 128;
        CP_ASYNC16(s_w0 + c4 * 16, W1p + c4 * 4);
    }
    CP_COMMIT();

#pragma unroll
    for (int i = 0; i < 16; i++) {
        int c = tid + i * 128;
        int nn = c >> 7, k4 = c & 127;
        uint2 raw = *(const uint2*)(g_Fh + (size_t)(n0 + nn) * 512 + k4 * 4);
        float2 f0 = __half22float2(*(__half2*)&raw.x);
        float2 f1 = __half22float2(*(__half2*)&raw.y);
        *(float4*)(scomb + nn * 576 + 64 + k4 * 4) = make_float4(f0.x, f0.y, f1.x, f1.y);
    }
    CP_WAIT0();
    __syncthreads();

    unsigned long long accA[8], accB[8];
#pragma unroll
    for (int n = 0; n < 8; n++) { accA[n] = 0ull; accB[n] = 0ull; }

    for (int kt = 0; kt < 9; kt++) {
        const float* nxt = (kt < 8) ? (W1p + (kt + 1) * 4096) : W2p;
        unsigned dstb = (kt & 1) ? s_w0 : smem_u32(wbuf1);
#pragma unroll
        for (int i = 0; i < 8; i++) {
            int c4 = tid + i * 128;
            CP_ASYNC16(dstb + c4 * 16, nxt + c4 * 4);
        }
        CP_COMMIT();

        const float* Wt = (kt & 1) ? wbuf1 : wbuf0;
#pragma unroll 4
        for (int kk4 = 0; kk4 < 16; kk4++) {
            float w0 = Wt[(kk4 * 4 + 0) * 64 + j];
            float w1 = Wt[(kk4 * 4 + 1) * 64 + j];
            float w2f = Wt[(kk4 * 4 + 2) * 64 + j];
            float w3 = Wt[(kk4 * 4 + 3) * 64 + j];
            unsigned long long wp01, wp23;
            PACK2(wp01, w0, w1);
            PACK2(wp23, w2f, w3);
#pragma unroll
            for (int n = 0; n < 8; n++) {
                ulonglong2 a = ((const ulonglong2*)(scomb + (g * 8 + n) * 576))[kt * 16 + kk4];
                FMA2(accA[n], wp01, a.x);
                FMA2(accB[n], wp23, a.y);
            }
        }
        CP_WAIT0();
        __syncthreads();
    }

    float bb = b1[l * 64 + j];
#pragma unroll
    for (int n = 0; n < 8; n++) {
        float lo, hi, lo2, hi2;
        UNPACK2(lo, hi, accA[n]);
        UNPACK2(lo2, hi2, accB[n]);
        scomb[(g * 8 + n) * 576 + 64 + j] = tanhf(bb + lo + hi + lo2 + hi2);
    }
    __syncthreads();

    const float* Wt2 = wbuf1;
    unsigned long long zA[8], zB[8];
#pragma unroll
    for (int n = 0; n < 8; n++) { zA[n] = 0ull; zB[n] = 0ull; }
#pragma unroll 4
    for (int kk4 = 0; kk4 < 16; kk4++) {
        float w0 = Wt2[(kk4 * 4 + 0) * 64 + j];
        float w1 = Wt2[(kk4 * 4 + 1) * 64 + j];
        float w2f = Wt2[(kk4 * 4 + 2) * 64 + j];
        float w3 = Wt2[(kk4 * 4 + 3) * 64 + j];
        unsigned long long wp01, wp23;
        PACK2(wp01, w0, w1);
        PACK2(wp23, w2f, w3);
#pragma unroll
        for (int n = 0; n < 8; n++) {
            ulonglong2 a = ((const ulonglong2*)(scomb + (g * 8 + n) * 576 + 64))[kk4];
            FMA2(zA[n], wp01, a.x);
            FMA2(zB[n], wp23, a.y);
        }
    }
    float z[8];
    float bb2 = b2[l * 64 + j];
#pragma unroll
    for (int n = 0; n < 8; n++) {
        float lo, hi, lo2, hi2;
        UNPACK2(lo, hi, zA[n]);
        UNPACK2(lo2, hi2, zB[n]);
        z[n] = bb2 + lo + hi + lo2 + hi2 + scomb[(g * 8 + n) * 576 + j];
    }

#pragma unroll
    for (int n = 0; n < 8; n++) {
        float a = z[n], bsq = z[n] * z[n];
#pragma unroll
        for (int o = 16; o; o >>= 1) {
            a += __shfl_down_sync(0xffffffffu, a, o);
            bsq += __shfl_down_sync(0xffffffffu, bsq, o);
        }
        if (lane == 0) {
            sRed[((g * 2 + w2) * 8 + n) * 2 + 0] = a;
            sRed[((g * 2 + w2) * 8 + n) * 2 + 1] = bsq;
        }
    }
    __syncthreads();

    float gj = lng[l * 64 + j];
    float bj = lnb[l * 64 + j];
#pragma unroll
    for (int n = 0; n < 8; n++) {
        float su = sRed[((g * 2 + 0) * 8 + n) * 2 + 0] + sRed[((g * 2 + 1) * 8 + n) * 2 + 0];
        float sq = sRed[((g * 2 + 0) * 8 + n) * 2 + 1] + sRed[((g * 2 + 1) * 8 + n) * 2 + 1];
        float mu = su * (1.f / 64.f);
        float var = sq * (1.f / 64.f) - mu * mu;
        float nrm = rsqrtf(var + 1e-5f);
        int n_ = n0 + g * 8 + n;
        hout[(size_t)n_ * 64 + j] = (z[n] - mu) * nrm * gj + bj;
    }
}

// ---------------- launch ----------------
extern "C" void kernel_launch(void* const* d_in, const int* in_sizes, int n_in,
                              void* d_out, int out_size) {
    const float* x   = (const float*)d_in[0];
    const int*   ei  = (const int*)d_in[1];
    const float* ew  = (const float*)d_in[2];
    const float* gW  = (const float*)d_in[3];
    const float* gas = (const float*)d_in[4];
    const float* gad = (const float*)d_in[5];
    const float* gb  = (const float*)d_in[6];
    const float* W1  = (const float*)d_in[7];
    const float* b1  = (const float*)d_in[8];
    const float* W2  = (const float*)d_in[9];
    const float* b2  = (const float*)d_in[10];
    const float* lg  = (const float*)d_in[11];
    const float* lb  = (const float*)d_in[12];
    float* out = (float*)d_out;

    const int mlp_smem = (16 * 576 + 4096 + 4096 + 64) * 4;   // 69888 B
    cudaFuncSetAttribute(k_mlp, cudaFuncAttributeMaxDynamicSharedMemorySize, mlp_smem);

    k_feat<<<dim3((NP + 63) / 64, RR), 128>>>(x, gW, gas, gad, 0, 1);
    k_hist<<<(EE + 255) / 256, 256>>>(ei, ew);
    k_scan<<<SCAN_BLOCKS, 512>>>();
    k_scatter<<<(EE + 255) / 256, 256>>>(ei, ew);

    k_gather<<<MM / 16, 256>>>(gb, 0);
    k_mlp<<<NN / 16, 128, mlp_smem>>>(x, W1, b1, W2, b2, lg, lb, 0, out, 0, 1);

    // layer 1
    k_feat<<<dim3((NP + 63) / 64, RR), 128>>>(x, gW, gas, gad, 1, 0);
    k_gather<<<MM / 16, 256>>>(gb, 1);
    k_mlp<<<NN / 16, 128, mlp_smem>>>(x, W1, b1, W2, b2, lg, lb, 1, out, 1, 0);
}